// round 1
// baseline (speedup 1.0000x reference)
#include <cuda_runtime.h>
#include <cuda_bf16.h>
#include <math.h>

// Problem constants
#define NTOK 4096      // B*S
#define DMODEL 1024
#define D3 3072
#define NHEAD 16
#define HDIM 64
#define SEQ 1024
#define NB 4
#define NTILES 8
#define DFF 4096

// ---------------- scratch (static device globals; no allocation) -------------
__device__ float g_n1[NTOK * DMODEL];
__device__ float g_qkv[NTOK * D3];
__device__ float g_attn[NTOK * DMODEL];
__device__ float g_xres[NTOK * DMODEL];
__device__ float g_n2[NTOK * DMODEL];
__device__ float g_h[(size_t)NTOK * DFF];
__device__ int g_tile_id[NTOK];
__device__ int g_perm[NTOK];
__device__ int g_cnt[NTILES];
__device__ int g_off[NTILES];
__device__ int g_fill[NTILES];

// ---------------- layernorm ------------------------------------------------
__global__ void ln_kernel(const float* __restrict__ x, const float* __restrict__ g,
                          const float* __restrict__ bb, float* __restrict__ y) {
    int t = blockIdx.x;
    const float* xr = x + (size_t)t * DMODEL;
    float s = 0.f, s2 = 0.f;
#pragma unroll
    for (int i = 0; i < 4; i++) {
        float v = xr[threadIdx.x + i * 256];
        s += v; s2 += v * v;
    }
#pragma unroll
    for (int o = 16; o; o >>= 1) {
        s  += __shfl_xor_sync(0xffffffffu, s,  o);
        s2 += __shfl_xor_sync(0xffffffffu, s2, o);
    }
    __shared__ float rs[8], rq[8];
    if ((threadIdx.x & 31) == 0) { rs[threadIdx.x >> 5] = s; rq[threadIdx.x >> 5] = s2; }
    __syncthreads();
    __shared__ float smean, srstd;
    if (threadIdx.x == 0) {
        float a = 0.f, b2 = 0.f;
#pragma unroll
        for (int i = 0; i < 8; i++) { a += rs[i]; b2 += rq[i]; }
        float mean = a * (1.f / DMODEL);
        float var = b2 * (1.f / DMODEL) - mean * mean;
        smean = mean; srstd = rsqrtf(var + 1e-5f);
    }
    __syncthreads();
    float mean = smean, rstd = srstd;
    float* yr = y + (size_t)t * DMODEL;
#pragma unroll
    for (int i = 0; i < 4; i++) {
        int d = threadIdx.x + i * 256;
        yr[d] = (xr[d] - mean) * rstd * g[d] + bb[d];
    }
}

// ---------------- NT GEMM: C[m][n] = sum_k A[m][k]*W[n][k] + bias[n] (+resid)
template <bool RESID>
__global__ void gemm_nt(const float* __restrict__ A, const float* __restrict__ W,
                        const float* __restrict__ bias, const float* __restrict__ resid,
                        float* __restrict__ C, int M, int N, int K) {
    __shared__ float As[16][68];
    __shared__ float Ws[16][68];
    int bm = blockIdx.y * 64, bn = blockIdx.x * 64;
    int tid = threadIdx.x;
    int ty = tid >> 4, tx = tid & 15;
    int lr = tid >> 2, lk = (tid & 3) * 4;
    float acc[4][4] = {};
    const float* Arow = A + (size_t)(bm + lr) * K + lk;
    const float* Wrow = W + (size_t)(bn + lr) * K + lk;
    for (int k0 = 0; k0 < K; k0 += 16) {
        float4 av = *(const float4*)(Arow + k0);
        float4 wv = *(const float4*)(Wrow + k0);
        As[lk + 0][lr] = av.x; As[lk + 1][lr] = av.y; As[lk + 2][lr] = av.z; As[lk + 3][lr] = av.w;
        Ws[lk + 0][lr] = wv.x; Ws[lk + 1][lr] = wv.y; Ws[lk + 2][lr] = wv.z; Ws[lk + 3][lr] = wv.w;
        __syncthreads();
#pragma unroll
        for (int kk = 0; kk < 16; kk++) {
            float4 a4 = *(const float4*)&As[kk][ty * 4];
            float4 b4 = *(const float4*)&Ws[kk][tx * 4];
            float av_[4] = {a4.x, a4.y, a4.z, a4.w};
            float bv_[4] = {b4.x, b4.y, b4.z, b4.w};
#pragma unroll
            for (int i = 0; i < 4; i++)
#pragma unroll
                for (int j = 0; j < 4; j++) acc[i][j] += av_[i] * bv_[j];
        }
        __syncthreads();
    }
#pragma unroll
    for (int i = 0; i < 4; i++) {
        int m = bm + ty * 4 + i;
#pragma unroll
        for (int j = 0; j < 4; j++) {
            int n = bn + tx * 4 + j;
            float v = acc[i][j] + bias[n];
            if (RESID) v += resid[(size_t)m * N + n];
            C[(size_t)m * N + n] = v;
        }
    }
}

// ---------------- flash attention (fp32, hd=64, online softmax) -------------
__global__ void attn_kernel(const float* __restrict__ qkv, float* __restrict__ outp) {
    extern __shared__ float sm[];
    float (*Qs)[64] = (float(*)[64])(sm);
    float (*Ps)[64] = (float(*)[64])(sm + 4096);
    float (*Ks)[68] = (float(*)[68])(sm + 8192);
    float (*Vs)[68] = (float(*)[68])(sm + 8192 + 64 * 68);

    int qt = blockIdx.x, h = blockIdx.y, b = blockIdx.z;
    int tid = threadIdx.x, ty = tid >> 4, tx = tid & 15;
    int tok0 = b * SEQ + qt * 64;

#pragma unroll
    for (int i = 0; i < 4; i++) {
        int lin = tid + i * 256;
        int r = lin >> 4, c = (lin & 15) << 2;
        float4 v = *(const float4*)(qkv + (size_t)(tok0 + r) * D3 + h * HDIM + c);
        Qs[r][c] = v.x; Qs[r][c + 1] = v.y; Qs[r][c + 2] = v.z; Qs[r][c + 3] = v.w;
    }

    float m_[4], l_[4], O[4][4];
#pragma unroll
    for (int i = 0; i < 4; i++) {
        m_[i] = -1e30f; l_[i] = 0.f;
#pragma unroll
        for (int j = 0; j < 4; j++) O[i][j] = 0.f;
    }
    const float scale = 0.125f;  // 1/sqrt(64)

    for (int kt = 0; kt < 16; kt++) {
        int kb = b * SEQ + kt * 64;
#pragma unroll
        for (int i = 0; i < 4; i++) {
            int lin = tid + i * 256;
            int r = lin >> 4, c = (lin & 15) << 2;
            const float* base = qkv + (size_t)(kb + r) * D3 + h * HDIM + c;
            float4 kv = *(const float4*)(base + DMODEL);
            Ks[r][c] = kv.x; Ks[r][c + 1] = kv.y; Ks[r][c + 2] = kv.z; Ks[r][c + 3] = kv.w;
            float4 vv = *(const float4*)(base + 2 * DMODEL);
            Vs[r][c] = vv.x; Vs[r][c + 1] = vv.y; Vs[r][c + 2] = vv.z; Vs[r][c + 3] = vv.w;
        }
        __syncthreads();

        float S[4][4] = {};
#pragma unroll
        for (int k4 = 0; k4 < 16; k4++) {
            float qv[4][4], kv[4][4];
#pragma unroll
            for (int i = 0; i < 4; i++) {
                float4 q4 = *(const float4*)&Qs[ty * 4 + i][k4 * 4];
                qv[i][0] = q4.x; qv[i][1] = q4.y; qv[i][2] = q4.z; qv[i][3] = q4.w;
            }
#pragma unroll
            for (int j = 0; j < 4; j++) {
                float4 k4v = *(const float4*)&Ks[tx * 4 + j][k4 * 4];
                kv[j][0] = k4v.x; kv[j][1] = k4v.y; kv[j][2] = k4v.z; kv[j][3] = k4v.w;
            }
#pragma unroll
            for (int i = 0; i < 4; i++)
#pragma unroll
                for (int j = 0; j < 4; j++)
#pragma unroll
                    for (int c = 0; c < 4; c++) S[i][j] += qv[i][c] * kv[j][c];
        }

#pragma unroll
        for (int i = 0; i < 4; i++) {
#pragma unroll
            for (int j = 0; j < 4; j++) S[i][j] *= scale;
            float rm = fmaxf(fmaxf(S[i][0], S[i][1]), fmaxf(S[i][2], S[i][3]));
#pragma unroll
            for (int o2 = 1; o2 < 16; o2 <<= 1) rm = fmaxf(rm, __shfl_xor_sync(0xffffffffu, rm, o2));
            float mn = fmaxf(m_[i], rm);
            float fac = __expf(m_[i] - mn);
            float rsum = 0.f;
#pragma unroll
            for (int j = 0; j < 4; j++) {
                float p = __expf(S[i][j] - mn);
                Ps[ty * 4 + i][tx * 4 + j] = p;
                rsum += p;
            }
#pragma unroll
            for (int o2 = 1; o2 < 16; o2 <<= 1) rsum += __shfl_xor_sync(0xffffffffu, rsum, o2);
            l_[i] = l_[i] * fac + rsum;
            m_[i] = mn;
#pragma unroll
            for (int j = 0; j < 4; j++) O[i][j] *= fac;
        }
        __syncthreads();

#pragma unroll
        for (int k4 = 0; k4 < 16; k4++) {
            float pA[4][4];
#pragma unroll
            for (int i = 0; i < 4; i++) {
                float4 p4 = *(const float4*)&Ps[ty * 4 + i][k4 * 4];
                pA[i][0] = p4.x; pA[i][1] = p4.y; pA[i][2] = p4.z; pA[i][3] = p4.w;
            }
#pragma unroll
            for (int kc = 0; kc < 4; kc++) {
                float4 vv = *(const float4*)&Vs[k4 * 4 + kc][tx * 4];
                float vB[4] = {vv.x, vv.y, vv.z, vv.w};
#pragma unroll
                for (int i = 0; i < 4; i++)
#pragma unroll
                    for (int j = 0; j < 4; j++) O[i][j] += pA[i][kc] * vB[j];
            }
        }
        __syncthreads();
    }

#pragma unroll
    for (int i = 0; i < 4; i++) {
        float invl = 1.f / l_[i];
        int tok = tok0 + ty * 4 + i;
#pragma unroll
        for (int j = 0; j < 4; j++)
            outp[(size_t)tok * DMODEL + h * HDIM + tx * 4 + j] = O[i][j] * invl;
    }
}

// ---------------- gate: logits, argmax, one-hot, histogram ------------------
__global__ void zero_kernel() {
    if (threadIdx.x < NTILES) { g_cnt[threadIdx.x] = 0; g_fill[threadIdx.x] = 0; }
}

__global__ void gate_kernel(const float* __restrict__ n2, const float* __restrict__ gw,
                            const float* __restrict__ gb, float* __restrict__ gate_out) {
    int t = blockIdx.x;
    const float* xr = n2 + (size_t)t * DMODEL;
    float lg[NTILES] = {};
    for (int d = threadIdx.x; d < DMODEL; d += 256) {
        float v = xr[d];
#pragma unroll
        for (int e = 0; e < NTILES; e++) lg[e] += v * gw[e * DMODEL + d];
    }
#pragma unroll
    for (int o = 16; o; o >>= 1)
#pragma unroll
        for (int e = 0; e < NTILES; e++) lg[e] += __shfl_xor_sync(0xffffffffu, lg[e], o);
    __shared__ float smv[8][NTILES];
    if ((threadIdx.x & 31) == 0)
#pragma unroll
        for (int e = 0; e < NTILES; e++) smv[threadIdx.x >> 5][e] = lg[e];
    __syncthreads();
    if (threadIdx.x == 0) {
        float vals[NTILES];
        int best = 0; float bv = -1e30f;
#pragma unroll
        for (int e = 0; e < NTILES; e++) {
            float v = gb[e];
#pragma unroll
            for (int w = 0; w < 8; w++) v += smv[w][e];
            vals[e] = v;
            if (v > bv) { bv = v; best = e; }
        }
        g_tile_id[t] = best;
#pragma unroll
        for (int e = 0; e < NTILES; e++) gate_out[(size_t)t * NTILES + e] = (e == best) ? 1.f : 0.f;
        atomicAdd(&g_cnt[best], 1);
        (void)vals;
    }
}

__global__ void scan_kernel() {
    if (threadIdx.x == 0) {
        int a = 0;
        for (int e = 0; e < NTILES; e++) { g_off[e] = a; a += g_cnt[e]; }
    }
}

__global__ void scatter_kernel() {
    int t = blockIdx.x * 256 + threadIdx.x;
    int e = g_tile_id[t];
    int p = atomicAdd(&g_fill[e], 1);
    g_perm[g_off[e] + p] = t;
}

// ---------------- FFN up: h = relu(n2[perm] @ up_W[t] + up_b[t]) -------------
__global__ void ffn_up_kernel(const float* __restrict__ n2, const float* __restrict__ upW,
                              const float* __restrict__ upb) {
    int t = blockIdx.z;
    int cnt = g_cnt[t];
    int bm = blockIdx.y * 64;
    if (bm >= cnt) return;
    int off = g_off[t];
    int bn = blockIdx.x * 64;
    const float* B = upW + (size_t)t * DMODEL * DFF;

    __shared__ float As[16][68];
    __shared__ float Bs[16][68];
    int tid = threadIdx.x, ty = tid >> 4, tx = tid & 15;
    int lr = tid >> 2, lk = (tid & 3) * 4;
    int lkb = tid >> 4, lnb = (tid & 15) * 4;
    int arow = bm + lr;
    int tok = (arow < cnt) ? g_perm[off + arow] : -1;
    float acc[4][4] = {};

    for (int k0 = 0; k0 < DMODEL; k0 += 16) {
        float4 av = make_float4(0.f, 0.f, 0.f, 0.f);
        if (tok >= 0) av = *(const float4*)(n2 + (size_t)tok * DMODEL + k0 + lk);
        As[lk + 0][lr] = av.x; As[lk + 1][lr] = av.y; As[lk + 2][lr] = av.z; As[lk + 3][lr] = av.w;
        float4 bv = *(const float4*)(B + (size_t)(k0 + lkb) * DFF + bn + lnb);
        *(float4*)&Bs[lkb][lnb] = bv;
        __syncthreads();
#pragma unroll
        for (int kk = 0; kk < 16; kk++) {
            float4 a4 = *(const float4*)&As[kk][ty * 4];
            float4 b4 = *(const float4*)&Bs[kk][tx * 4];
            float av_[4] = {a4.x, a4.y, a4.z, a4.w};
            float bv_[4] = {b4.x, b4.y, b4.z, b4.w};
#pragma unroll
            for (int i = 0; i < 4; i++)
#pragma unroll
                for (int j = 0; j < 4; j++) acc[i][j] += av_[i] * bv_[j];
        }
        __syncthreads();
    }
#pragma unroll
    for (int i = 0; i < 4; i++) {
        int r = bm + ty * 4 + i;
        if (r < cnt) {
#pragma unroll
            for (int j = 0; j < 4; j++) {
                int n = bn + tx * 4 + j;
                float v = acc[i][j] + upb[t * DFF + n];
                g_h[(size_t)(off + r) * DFF + n] = fmaxf(v, 0.f);
            }
        }
    }
}

// ---------------- FFN down: out[perm] = xres[perm] + h @ down_W[t] + down_b[t]
__global__ void ffn_down_kernel(const float* __restrict__ dW, const float* __restrict__ db,
                                const float* __restrict__ xres, float* __restrict__ outp) {
    int t = blockIdx.z;
    int cnt = g_cnt[t];
    int bm = blockIdx.y * 64;
    if (bm >= cnt) return;
    int off = g_off[t];
    int bn = blockIdx.x * 64;
    const float* B = dW + (size_t)t * DFF * DMODEL;

    __shared__ float As[16][68];
    __shared__ float Bs[16][68];
    int tid = threadIdx.x, ty = tid >> 4, tx = tid & 15;
    int lr = tid >> 2, lk = (tid & 3) * 4;
    int lkb = tid >> 4, lnb = (tid & 15) * 4;
    int arow = bm + lr;
    bool avalid = (arow < cnt);
    float acc[4][4] = {};

    for (int k0 = 0; k0 < DFF; k0 += 16) {
        float4 av = make_float4(0.f, 0.f, 0.f, 0.f);
        if (avalid) av = *(const float4*)(g_h + (size_t)(off + arow) * DFF + k0 + lk);
        As[lk + 0][lr] = av.x; As[lk + 1][lr] = av.y; As[lk + 2][lr] = av.z; As[lk + 3][lr] = av.w;
        float4 bv = *(const float4*)(B + (size_t)(k0 + lkb) * DMODEL + bn + lnb);
        *(float4*)&Bs[lkb][lnb] = bv;
        __syncthreads();
#pragma unroll
        for (int kk = 0; kk < 16; kk++) {
            float4 a4 = *(const float4*)&As[kk][ty * 4];
            float4 b4 = *(const float4*)&Bs[kk][tx * 4];
            float av_[4] = {a4.x, a4.y, a4.z, a4.w};
            float bv_[4] = {b4.x, b4.y, b4.z, b4.w};
#pragma unroll
            for (int i = 0; i < 4; i++)
#pragma unroll
                for (int j = 0; j < 4; j++) acc[i][j] += av_[i] * bv_[j];
        }
        __syncthreads();
    }
#pragma unroll
    for (int i = 0; i < 4; i++) {
        int r = bm + ty * 4 + i;
        if (r < cnt) {
            int tok = g_perm[off + r];
#pragma unroll
            for (int j = 0; j < 4; j++) {
                int n = bn + tx * 4 + j;
                outp[(size_t)tok * DMODEL + n] =
                    acc[i][j] + db[t * DMODEL + n] + xres[(size_t)tok * DMODEL + n];
            }
        }
    }
}

// ---------------- launch ----------------------------------------------------
extern "C" void kernel_launch(void* const* d_in, const int* in_sizes, int n_in,
                              void* d_out, int out_size) {
    const float* x      = (const float*)d_in[0];
    const float* ln1_g  = (const float*)d_in[1];
    const float* ln1_b  = (const float*)d_in[2];
    const float* qkv_w  = (const float*)d_in[3];
    const float* qkv_b  = (const float*)d_in[4];
    const float* out_w  = (const float*)d_in[5];
    const float* out_b  = (const float*)d_in[6];
    const float* ln2_g  = (const float*)d_in[7];
    const float* ln2_b  = (const float*)d_in[8];
    const float* gate_w = (const float*)d_in[9];
    const float* gate_b = (const float*)d_in[10];
    const float* up_W   = (const float*)d_in[11];
    const float* up_b   = (const float*)d_in[12];
    const float* down_W = (const float*)d_in[13];
    const float* down_b = (const float*)d_in[14];

    float* outp = (float*)d_out;
    float* gate_out = outp + (size_t)NTOK * DMODEL;

    void* p;
    cudaGetSymbolAddress(&p, g_n1);   float* n1   = (float*)p;
    cudaGetSymbolAddress(&p, g_qkv);  float* qkv  = (float*)p;
    cudaGetSymbolAddress(&p, g_attn); float* attn = (float*)p;
    cudaGetSymbolAddress(&p, g_xres); float* xres = (float*)p;
    cudaGetSymbolAddress(&p, g_n2);   float* n2   = (float*)p;

    // 1) LN1
    ln_kernel<<<NTOK, 256>>>(x, ln1_g, ln1_b, n1);
    // 2) QKV projection
    gemm_nt<false><<<dim3(D3 / 64, NTOK / 64), 256>>>(n1, qkv_w, qkv_b, nullptr, qkv,
                                                      NTOK, D3, DMODEL);
    // 3) attention
    const int smem_attn = (4096 + 4096 + 64 * 68 + 64 * 68) * 4;  // 67584 B
    cudaFuncSetAttribute(attn_kernel, cudaFuncAttributeMaxDynamicSharedMemorySize, smem_attn);
    attn_kernel<<<dim3(SEQ / 64, NHEAD, NB), 256, smem_attn>>>(qkv, attn);
    // 4) out projection + residual
    gemm_nt<true><<<dim3(DMODEL / 64, NTOK / 64), 256>>>(attn, out_w, out_b, x, xres,
                                                         NTOK, DMODEL, DMODEL);
    // 5) LN2
    ln_kernel<<<NTOK, 256>>>(xres, ln2_g, ln2_b, n2);
    // 6) gate + bucketing
    zero_kernel<<<1, 32>>>();
    gate_kernel<<<NTOK, 256>>>(n2, gate_w, gate_b, gate_out);
    scan_kernel<<<1, 32>>>();
    scatter_kernel<<<NTOK / 256, 256>>>();
    // 7) FFN
    ffn_up_kernel<<<dim3(DFF / 64, NTOK / 64, NTILES), 256>>>(n2, up_W, up_b);
    ffn_down_kernel<<<dim3(DMODEL / 64, NTOK / 64, NTILES), 256>>>(down_W, down_b, xres, outp);
}

// round 2
// speedup vs baseline: 1.7853x; 1.7853x over previous
#include <cuda_runtime.h>
#include <cuda_bf16.h>
#include <math.h>
#include <stdint.h>

#define NTOK 4096
#define DMODEL 1024
#define D3 3072
#define NHEAD 16
#define HDIM 64
#define SEQ 1024
#define NB 4
#define NTILES 8
#define DFF 4096

// ---------------- scratch ----------------------------------------------------
__device__ float g_n1[NTOK * DMODEL];
__device__ float g_qkv[NTOK * D3];
__device__ float g_attn[NTOK * DMODEL];
__device__ float g_xres[NTOK * DMODEL];
__device__ float g_n2[NTOK * DMODEL];
__device__ __nv_bfloat16 g_h_hi[(size_t)NTOK * DFF];
__device__ __nv_bfloat16 g_h_lo[(size_t)NTOK * DFF];
__device__ int g_tile_id[NTOK];
__device__ int g_perm[NTOK];
__device__ int g_cnt[NTILES];
__device__ int g_off[NTILES];
__device__ int g_fill[NTILES];

// ---------------- mma helpers -------------------------------------------------
__device__ __forceinline__ uint32_t sptr(const void* p) {
    return (uint32_t)__cvta_generic_to_shared(p);
}
__device__ __forceinline__ void ldsm4(uint32_t* r, uint32_t a) {
    asm volatile("ldmatrix.sync.aligned.m8n8.x4.shared.b16 {%0,%1,%2,%3}, [%4];"
                 : "=r"(r[0]), "=r"(r[1]), "=r"(r[2]), "=r"(r[3]) : "r"(a));
}
__device__ __forceinline__ void ldsm4t(uint32_t* r, uint32_t a) {
    asm volatile("ldmatrix.sync.aligned.m8n8.x4.trans.shared.b16 {%0,%1,%2,%3}, [%4];"
                 : "=r"(r[0]), "=r"(r[1]), "=r"(r[2]), "=r"(r[3]) : "r"(a));
}
__device__ __forceinline__ void mma16816(float* c, const uint32_t* a, const uint32_t* b) {
    asm volatile(
        "mma.sync.aligned.m16n8k16.row.col.f32.bf16.bf16.f32 "
        "{%0,%1,%2,%3}, {%4,%5,%6,%7}, {%8,%9}, {%0,%1,%2,%3};"
        : "+f"(c[0]), "+f"(c[1]), "+f"(c[2]), "+f"(c[3])
        : "r"(a[0]), "r"(a[1]), "r"(a[2]), "r"(a[3]), "r"(b[0]), "r"(b[1]));
}
__device__ __forceinline__ uint32_t pack_bf2(__nv_bfloat16 a, __nv_bfloat16 b) {
    return (uint32_t)__bfloat16_as_ushort(a) | ((uint32_t)__bfloat16_as_ushort(b) << 16);
}
// split fp32 -> bf16 hi + bf16 lo (two-term compensated)
__device__ __forceinline__ void split4(float4 v, __nv_bfloat16* hi, __nv_bfloat16* lo) {
    float a[4] = {v.x, v.y, v.z, v.w};
    __nv_bfloat16 h[4], l[4];
#pragma unroll
    for (int i = 0; i < 4; i++) {
        h[i] = __float2bfloat16(a[i]);
        l[i] = __float2bfloat16(a[i] - __bfloat162float(h[i]));
    }
    *(uint32_t*)(hi)     = pack_bf2(h[0], h[1]);
    *(uint32_t*)(hi + 2) = pack_bf2(h[2], h[3]);
    *(uint32_t*)(lo)     = pack_bf2(l[0], l[1]);
    *(uint32_t*)(lo + 2) = pack_bf2(l[2], l[3]);
}
__device__ __forceinline__ void split2_store(__nv_bfloat16* hi, __nv_bfloat16* lo,
                                             float v0, float v1) {
    __nv_bfloat16 h0 = __float2bfloat16(v0), h1 = __float2bfloat16(v1);
    __nv_bfloat16 l0 = __float2bfloat16(v0 - __bfloat162float(h0));
    __nv_bfloat16 l1 = __float2bfloat16(v1 - __bfloat162float(h1));
    *(uint32_t*)hi = pack_bf2(h0, h1);
    *(uint32_t*)lo = pack_bf2(l0, l1);
}

// compute one 32-wide K step: 2 x k16 substeps, hi/lo compensated (3 mma passes)
template <bool BT, int BSTR>
__device__ __forceinline__ void mma_compute(const __nv_bfloat16* As_hi, const __nv_bfloat16* As_lo,
                                            const __nv_bfloat16* Bs_hi, const __nv_bfloat16* Bs_lo,
                                            float (*acc)[4][4], int lane, int wm, int wn) {
#pragma unroll
    for (int s = 0; s < 2; s++) {
        const int ks = s * 16;
        uint32_t ah[4][4], al[4][4], bh[4][2], bl[4][2];
#pragma unroll
        for (int mi = 0; mi < 4; mi++) {
            int row = wm * 64 + mi * 16 + (lane & 15);
            int col = ks + ((lane >> 4) & 1) * 8;
            ldsm4(ah[mi], sptr(As_hi + row * 40 + col));
            ldsm4(al[mi], sptr(As_lo + row * 40 + col));
        }
#pragma unroll
        for (int p = 0; p < 2; p++) {
            uint32_t r[4];
            uint32_t adr_h, adr_l;
            if (!BT) {
                int n = wn * 32 + p * 16 + ((lane >> 4) & 1) * 8 + (lane & 7);
                int col = ks + ((lane >> 3) & 1) * 8;
                adr_h = sptr(Bs_hi + n * BSTR + col);
                adr_l = sptr(Bs_lo + n * BSTR + col);
                ldsm4(r, adr_h);
            } else {
                int k = ks + ((lane >> 3) & 1) * 8 + (lane & 7);
                int n = wn * 32 + p * 16 + ((lane >> 4) & 1) * 8;
                adr_h = sptr(Bs_hi + k * BSTR + n);
                adr_l = sptr(Bs_lo + k * BSTR + n);
                ldsm4t(r, adr_h);
            }
            bh[2 * p][0] = r[0]; bh[2 * p][1] = r[1];
            bh[2 * p + 1][0] = r[2]; bh[2 * p + 1][1] = r[3];
            if (!BT) ldsm4(r, adr_l); else ldsm4t(r, adr_l);
            bl[2 * p][0] = r[0]; bl[2 * p][1] = r[1];
            bl[2 * p + 1][0] = r[2]; bl[2 * p + 1][1] = r[3];
        }
#pragma unroll
        for (int mi = 0; mi < 4; mi++)
#pragma unroll
            for (int ni = 0; ni < 4; ni++) {
                mma16816(acc[mi][ni], ah[mi], bh[ni]);
                mma16816(acc[mi][ni], ah[mi], bl[ni]);
                mma16816(acc[mi][ni], al[mi], bh[ni]);
            }
    }
}

// ---------------- NT GEMM (A [M,K], W [N,K]) via HMMA ------------------------
template <bool RESID>
__global__ __launch_bounds__(256, 1) void mma_gemm_nt(const float* __restrict__ A,
                                                      const float* __restrict__ W,
                                                      const float* __restrict__ bias,
                                                      const float* __restrict__ resid,
                                                      float* __restrict__ C, int N, int K) {
    __shared__ __align__(16) __nv_bfloat16 As_hi[128 * 40], As_lo[128 * 40];
    __shared__ __align__(16) __nv_bfloat16 Bs_hi[128 * 40], Bs_lo[128 * 40];
    const int tid = threadIdx.x, lane = tid & 31, w = tid >> 5;
    const int wm = w & 1, wn = w >> 1;
    const int bm = blockIdx.y * 128, bn = blockIdx.x * 128;
    float acc[4][4][4] = {};
    float4 pa[4], pb[4];
#pragma unroll
    for (int i = 0; i < 4; i++) {
        int idx = tid + i * 256, row = idx >> 3, kc = idx & 7;
        pa[i] = *(const float4*)(A + (size_t)(bm + row) * K + kc * 4);
        pb[i] = *(const float4*)(W + (size_t)(bn + row) * K + kc * 4);
    }
    for (int kt = 0;;) {
#pragma unroll
        for (int i = 0; i < 4; i++) {
            int idx = tid + i * 256, row = idx >> 3, kc = idx & 7;
            split4(pa[i], As_hi + row * 40 + kc * 4, As_lo + row * 40 + kc * 4);
            split4(pb[i], Bs_hi + row * 40 + kc * 4, Bs_lo + row * 40 + kc * 4);
        }
        __syncthreads();
        kt += 32;
        if (kt < K) {
#pragma unroll
            for (int i = 0; i < 4; i++) {
                int idx = tid + i * 256, row = idx >> 3, kc = idx & 7;
                pa[i] = *(const float4*)(A + (size_t)(bm + row) * K + kt + kc * 4);
                pb[i] = *(const float4*)(W + (size_t)(bn + row) * K + kt + kc * 4);
            }
        }
        mma_compute<false, 40>(As_hi, As_lo, Bs_hi, Bs_lo, acc, lane, wm, wn);
        __syncthreads();
        if (kt >= K) break;
    }
#pragma unroll
    for (int mi = 0; mi < 4; mi++) {
        int r0 = bm + wm * 64 + mi * 16 + (lane >> 2);
#pragma unroll
        for (int ni = 0; ni < 4; ni++) {
            int cn = bn + wn * 32 + ni * 8 + (lane & 3) * 2;
            float2 bs = *(const float2*)(bias + cn);
            float2 o0 = make_float2(acc[mi][ni][0] + bs.x, acc[mi][ni][1] + bs.y);
            float2 o1 = make_float2(acc[mi][ni][2] + bs.x, acc[mi][ni][3] + bs.y);
            if (RESID) {
                float2 ra = *(const float2*)(resid + (size_t)r0 * N + cn);
                float2 rb = *(const float2*)(resid + (size_t)(r0 + 8) * N + cn);
                o0.x += ra.x; o0.y += ra.y; o1.x += rb.x; o1.y += rb.y;
            }
            *(float2*)(C + (size_t)r0 * N + cn) = o0;
            *(float2*)(C + (size_t)(r0 + 8) * N + cn) = o1;
        }
    }
}

// ---------------- FFN up: gathered A (fp32), B = up_W[t] [K,N] ----------------
__global__ __launch_bounds__(256, 1) void mma_ffn_up(const float* __restrict__ n2,
                                                     const float* __restrict__ upW,
                                                     const float* __restrict__ upb,
                                                     __nv_bfloat16* __restrict__ Hh,
                                                     __nv_bfloat16* __restrict__ Hl) {
    const int t = blockIdx.z;
    const int cnt = g_cnt[t];
    const int bm = blockIdx.y * 128;
    if (bm >= cnt) return;
    const int off = g_off[t];
    const int bn = blockIdx.x * 128;
    const float* B = upW + (size_t)t * DMODEL * DFF;
    __shared__ __align__(16) __nv_bfloat16 As_hi[128 * 40], As_lo[128 * 40];
    __shared__ __align__(16) __nv_bfloat16 Bs_hi[32 * 136], Bs_lo[32 * 136];
    const int tid = threadIdx.x, lane = tid & 31, w = tid >> 5;
    const int wm = w & 1, wn = w >> 1;
    float acc[4][4][4] = {};
    int tokA[4];
#pragma unroll
    for (int i = 0; i < 4; i++) {
        int idx = tid + i * 256, row = idx >> 3, gr = bm + row;
        tokA[i] = (gr < cnt) ? g_perm[off + gr] : -1;
    }
    float4 pa[4], pb[4];
#pragma unroll
    for (int i = 0; i < 4; i++) {
        int idx = tid + i * 256, kc = idx & 7;
        pa[i] = (tokA[i] >= 0) ? *(const float4*)(n2 + (size_t)tokA[i] * DMODEL + kc * 4)
                               : make_float4(0.f, 0.f, 0.f, 0.f);
        int k = idx >> 5, nc = idx & 31;
        pb[i] = *(const float4*)(B + (size_t)k * DFF + bn + nc * 4);
    }
    for (int kt = 0;;) {
#pragma unroll
        for (int i = 0; i < 4; i++) {
            int idx = tid + i * 256, row = idx >> 3, kc = idx & 7;
            split4(pa[i], As_hi + row * 40 + kc * 4, As_lo + row * 40 + kc * 4);
            int k = idx >> 5, nc = idx & 31;
            split4(pb[i], Bs_hi + k * 136 + nc * 4, Bs_lo + k * 136 + nc * 4);
        }
        __syncthreads();
        kt += 32;
        if (kt < DMODEL) {
#pragma unroll
            for (int i = 0; i < 4; i++) {
                int idx = tid + i * 256, kc = idx & 7;
                pa[i] = (tokA[i] >= 0)
                            ? *(const float4*)(n2 + (size_t)tokA[i] * DMODEL + kt + kc * 4)
                            : make_float4(0.f, 0.f, 0.f, 0.f);
                int k = idx >> 5, nc = idx & 31;
                pb[i] = *(const float4*)(B + (size_t)(kt + k) * DFF + bn + nc * 4);
            }
        }
        mma_compute<true, 136>(As_hi, As_lo, Bs_hi, Bs_lo, acc, lane, wm, wn);
        __syncthreads();
        if (kt >= DMODEL) break;
    }
#pragma unroll
    for (int mi = 0; mi < 4; mi++) {
        int r0 = bm + wm * 64 + mi * 16 + (lane >> 2);
#pragma unroll
        for (int ni = 0; ni < 4; ni++) {
            int cn = bn + wn * 32 + ni * 8 + (lane & 3) * 2;
            float2 bs = *(const float2*)(upb + (size_t)t * DFF + cn);
            if (r0 < cnt) {
                float v0 = fmaxf(acc[mi][ni][0] + bs.x, 0.f);
                float v1 = fmaxf(acc[mi][ni][1] + bs.y, 0.f);
                split2_store(Hh + (size_t)(off + r0) * DFF + cn,
                             Hl + (size_t)(off + r0) * DFF + cn, v0, v1);
            }
            if (r0 + 8 < cnt) {
                float v2 = fmaxf(acc[mi][ni][2] + bs.x, 0.f);
                float v3 = fmaxf(acc[mi][ni][3] + bs.y, 0.f);
                split2_store(Hh + (size_t)(off + r0 + 8) * DFF + cn,
                             Hl + (size_t)(off + r0 + 8) * DFF + cn, v2, v3);
            }
        }
    }
}

// ---------------- FFN down: A pre-split bf16 (h), B = down_W[t] [K,N] ---------
__global__ __launch_bounds__(256, 1) void mma_ffn_down(const __nv_bfloat16* __restrict__ Hh,
                                                       const __nv_bfloat16* __restrict__ Hl,
                                                       const float* __restrict__ dW,
                                                       const float* __restrict__ db,
                                                       const float* __restrict__ xres,
                                                       float* __restrict__ outp) {
    const int t = blockIdx.z;
    const int cnt = g_cnt[t];
    const int bm = blockIdx.y * 128;
    if (bm >= cnt) return;
    const int off = g_off[t];
    const int bn = blockIdx.x * 128;
    const float* B = dW + (size_t)t * DFF * DMODEL;
    __shared__ __align__(16) __nv_bfloat16 As_hi[128 * 40], As_lo[128 * 40];
    __shared__ __align__(16) __nv_bfloat16 Bs_hi[32 * 136], Bs_lo[32 * 136];
    const int tid = threadIdx.x, lane = tid & 31, w = tid >> 5;
    const int wm = w & 1, wn = w >> 1;
    float acc[4][4][4] = {};
    uint4 pah[2], pal[2];
    float4 pb[4];
    const uint4 z4 = make_uint4(0, 0, 0, 0);
#pragma unroll
    for (int i = 0; i < 2; i++) {
        int idx = tid + i * 256, row = idx >> 2, kc = idx & 3, gr = bm + row;
        if (gr < cnt) {
            pah[i] = *(const uint4*)(Hh + (size_t)(off + gr) * DFF + kc * 8);
            pal[i] = *(const uint4*)(Hl + (size_t)(off + gr) * DFF + kc * 8);
        } else { pah[i] = z4; pal[i] = z4; }
    }
#pragma unroll
    for (int i = 0; i < 4; i++) {
        int idx = tid + i * 256, k = idx >> 5, nc = idx & 31;
        pb[i] = *(const float4*)(B + (size_t)k * DMODEL + bn + nc * 4);
    }
    for (int kt = 0;;) {
#pragma unroll
        for (int i = 0; i < 2; i++) {
            int idx = tid + i * 256, row = idx >> 2, kc = idx & 3;
            *(uint4*)(As_hi + row * 40 + kc * 8) = pah[i];
            *(uint4*)(As_lo + row * 40 + kc * 8) = pal[i];
        }
#pragma unroll
        for (int i = 0; i < 4; i++) {
            int idx = tid + i * 256, k = idx >> 5, nc = idx & 31;
            split4(pb[i], Bs_hi + k * 136 + nc * 4, Bs_lo + k * 136 + nc * 4);
        }
        __syncthreads();
        kt += 32;
        if (kt < DFF) {
#pragma unroll
            for (int i = 0; i < 2; i++) {
                int idx = tid + i * 256, row = idx >> 2, kc = idx & 3, gr = bm + row;
                if (gr < cnt) {
                    pah[i] = *(const uint4*)(Hh + (size_t)(off + gr) * DFF + kt + kc * 8);
                    pal[i] = *(const uint4*)(Hl + (size_t)(off + gr) * DFF + kt + kc * 8);
                } else { pah[i] = z4; pal[i] = z4; }
            }
#pragma unroll
            for (int i = 0; i < 4; i++) {
                int idx = tid + i * 256, k = idx >> 5, nc = idx & 31;
                pb[i] = *(const float4*)(B + (size_t)(kt + k) * DMODEL + bn + nc * 4);
            }
        }
        mma_compute<true, 136>(As_hi, As_lo, Bs_hi, Bs_lo, acc, lane, wm, wn);
        __syncthreads();
        if (kt >= DFF) break;
    }
#pragma unroll
    for (int mi = 0; mi < 4; mi++) {
        int r0 = bm + wm * 64 + mi * 16 + (lane >> 2);
#pragma unroll
        for (int ni = 0; ni < 4; ni++) {
            int cn = bn + wn * 32 + ni * 8 + (lane & 3) * 2;
            float2 db2 = *(const float2*)(db + (size_t)t * DMODEL + cn);
            if (r0 < cnt) {
                int tok = g_perm[off + r0];
                float2 xr = *(const float2*)(xres + (size_t)tok * DMODEL + cn);
                *(float2*)(outp + (size_t)tok * DMODEL + cn) =
                    make_float2(acc[mi][ni][0] + db2.x + xr.x, acc[mi][ni][1] + db2.y + xr.y);
            }
            if (r0 + 8 < cnt) {
                int tok = g_perm[off + r0 + 8];
                float2 xr = *(const float2*)(xres + (size_t)tok * DMODEL + cn);
                *(float2*)(outp + (size_t)tok * DMODEL + cn) =
                    make_float2(acc[mi][ni][2] + db2.x + xr.x, acc[mi][ni][3] + db2.y + xr.y);
            }
        }
    }
}

// ---------------- layernorm ---------------------------------------------------
__global__ void ln_kernel(const float* __restrict__ x, const float* __restrict__ g,
                          const float* __restrict__ bb, float* __restrict__ y) {
    int t = blockIdx.x;
    const float* xr = x + (size_t)t * DMODEL;
    float s = 0.f, s2 = 0.f;
#pragma unroll
    for (int i = 0; i < 4; i++) {
        float v = xr[threadIdx.x + i * 256];
        s += v; s2 += v * v;
    }
#pragma unroll
    for (int o = 16; o; o >>= 1) {
        s += __shfl_xor_sync(0xffffffffu, s, o);
        s2 += __shfl_xor_sync(0xffffffffu, s2, o);
    }
    __shared__ float rs[8], rq[8];
    if ((threadIdx.x & 31) == 0) { rs[threadIdx.x >> 5] = s; rq[threadIdx.x >> 5] = s2; }
    __syncthreads();
    __shared__ float smean, srstd;
    if (threadIdx.x == 0) {
        float a = 0.f, b2 = 0.f;
#pragma unroll
        for (int i = 0; i < 8; i++) { a += rs[i]; b2 += rq[i]; }
        float mean = a * (1.f / DMODEL);
        float var = b2 * (1.f / DMODEL) - mean * mean;
        smean = mean; srstd = rsqrtf(var + 1e-5f);
    }
    __syncthreads();
    float mean = smean, rstd = srstd;
    float* yr = y + (size_t)t * DMODEL;
#pragma unroll
    for (int i = 0; i < 4; i++) {
        int d = threadIdx.x + i * 256;
        yr[d] = (xr[d] - mean) * rstd * g[d] + bb[d];
    }
}

// ---------------- flash attention (fp32) --------------------------------------
__global__ void attn_kernel(const float* __restrict__ qkv, float* __restrict__ outp) {
    extern __shared__ float sm[];
    float (*Qs)[64] = (float(*)[64])(sm);
    float (*Ps)[64] = (float(*)[64])(sm + 4096);
    float (*Ks)[68] = (float(*)[68])(sm + 8192);
    float (*Vs)[68] = (float(*)[68])(sm + 8192 + 64 * 68);

    int qt = blockIdx.x, h = blockIdx.y, b = blockIdx.z;
    int tid = threadIdx.x, ty = tid >> 4, tx = tid & 15;
    int tok0 = b * SEQ + qt * 64;

#pragma unroll
    for (int i = 0; i < 4; i++) {
        int lin = tid + i * 256;
        int r = lin >> 4, c = (lin & 15) << 2;
        float4 v = *(const float4*)(qkv + (size_t)(tok0 + r) * D3 + h * HDIM + c);
        Qs[r][c] = v.x; Qs[r][c + 1] = v.y; Qs[r][c + 2] = v.z; Qs[r][c + 3] = v.w;
    }

    float m_[4], l_[4], O[4][4];
#pragma unroll
    for (int i = 0; i < 4; i++) {
        m_[i] = -1e30f; l_[i] = 0.f;
#pragma unroll
        for (int j = 0; j < 4; j++) O[i][j] = 0.f;
    }
    const float scale = 0.125f;

    for (int kt = 0; kt < 16; kt++) {
        int kb = b * SEQ + kt * 64;
#pragma unroll
        for (int i = 0; i < 4; i++) {
            int lin = tid + i * 256;
            int r = lin >> 4, c = (lin & 15) << 2;
            const float* base = qkv + (size_t)(kb + r) * D3 + h * HDIM + c;
            float4 kv = *(const float4*)(base + DMODEL);
            Ks[r][c] = kv.x; Ks[r][c + 1] = kv.y; Ks[r][c + 2] = kv.z; Ks[r][c + 3] = kv.w;
            float4 vv = *(const float4*)(base + 2 * DMODEL);
            Vs[r][c] = vv.x; Vs[r][c + 1] = vv.y; Vs[r][c + 2] = vv.z; Vs[r][c + 3] = vv.w;
        }
        __syncthreads();

        float S[4][4] = {};
#pragma unroll
        for (int k4 = 0; k4 < 16; k4++) {
            float qv[4][4], kv[4][4];
#pragma unroll
            for (int i = 0; i < 4; i++) {
                float4 q4 = *(const float4*)&Qs[ty * 4 + i][k4 * 4];
                qv[i][0] = q4.x; qv[i][1] = q4.y; qv[i][2] = q4.z; qv[i][3] = q4.w;
            }
#pragma unroll
            for (int j = 0; j < 4; j++) {
                float4 k4v = *(const float4*)&Ks[tx * 4 + j][k4 * 4];
                kv[j][0] = k4v.x; kv[j][1] = k4v.y; kv[j][2] = k4v.z; kv[j][3] = k4v.w;
            }
#pragma unroll
            for (int i = 0; i < 4; i++)
#pragma unroll
                for (int j = 0; j < 4; j++)
#pragma unroll
                    for (int c = 0; c < 4; c++) S[i][j] += qv[i][c] * kv[j][c];
        }

#pragma unroll
        for (int i = 0; i < 4; i++) {
#pragma unroll
            for (int j = 0; j < 4; j++) S[i][j] *= scale;
            float rm = fmaxf(fmaxf(S[i][0], S[i][1]), fmaxf(S[i][2], S[i][3]));
#pragma unroll
            for (int o2 = 1; o2 < 16; o2 <<= 1) rm = fmaxf(rm, __shfl_xor_sync(0xffffffffu, rm, o2));
            float mn = fmaxf(m_[i], rm);
            float fac = __expf(m_[i] - mn);
            float rsum = 0.f;
#pragma unroll
            for (int j = 0; j < 4; j++) {
                float p = __expf(S[i][j] - mn);
                Ps[ty * 4 + i][tx * 4 + j] = p;
                rsum += p;
            }
#pragma unroll
            for (int o2 = 1; o2 < 16; o2 <<= 1) rsum += __shfl_xor_sync(0xffffffffu, rsum, o2);
            l_[i] = l_[i] * fac + rsum;
            m_[i] = mn;
#pragma unroll
            for (int j = 0; j < 4; j++) O[i][j] *= fac;
        }
        __syncthreads();

#pragma unroll
        for (int k4 = 0; k4 < 16; k4++) {
            float pA[4][4];
#pragma unroll
            for (int i = 0; i < 4; i++) {
                float4 p4 = *(const float4*)&Ps[ty * 4 + i][k4 * 4];
                pA[i][0] = p4.x; pA[i][1] = p4.y; pA[i][2] = p4.z; pA[i][3] = p4.w;
            }
#pragma unroll
            for (int kc = 0; kc < 4; kc++) {
                float4 vv = *(const float4*)&Vs[k4 * 4 + kc][tx * 4];
                float vB[4] = {vv.x, vv.y, vv.z, vv.w};
#pragma unroll
                for (int i = 0; i < 4; i++)
#pragma unroll
                    for (int j = 0; j < 4; j++) O[i][j] += pA[i][kc] * vB[j];
            }
        }
        __syncthreads();
    }

#pragma unroll
    for (int i = 0; i < 4; i++) {
        float invl = 1.f / l_[i];
        int tok = tok0 + ty * 4 + i;
#pragma unroll
        for (int j = 0; j < 4; j++)
            outp[(size_t)tok * DMODEL + h * HDIM + tx * 4 + j] = O[i][j] * invl;
    }
}

// ---------------- gate / bucketing --------------------------------------------
__global__ void zero_kernel() {
    if (threadIdx.x < NTILES) { g_cnt[threadIdx.x] = 0; g_fill[threadIdx.x] = 0; }
}

__global__ void gate_kernel(const float* __restrict__ n2, const float* __restrict__ gw,
                            const float* __restrict__ gb, float* __restrict__ gate_out) {
    int t = blockIdx.x;
    const float* xr = n2 + (size_t)t * DMODEL;
    float lg[NTILES] = {};
    for (int d = threadIdx.x; d < DMODEL; d += 256) {
        float v = xr[d];
#pragma unroll
        for (int e = 0; e < NTILES; e++) lg[e] += v * gw[e * DMODEL + d];
    }
#pragma unroll
    for (int o = 16; o; o >>= 1)
#pragma unroll
        for (int e = 0; e < NTILES; e++) lg[e] += __shfl_xor_sync(0xffffffffu, lg[e], o);
    __shared__ float smv[8][NTILES];
    if ((threadIdx.x & 31) == 0)
#pragma unroll
        for (int e = 0; e < NTILES; e++) smv[threadIdx.x >> 5][e] = lg[e];
    __syncthreads();
    if (threadIdx.x == 0) {
        int best = 0; float bv = -1e30f;
#pragma unroll
        for (int e = 0; e < NTILES; e++) {
            float v = gb[e];
#pragma unroll
            for (int w = 0; w < 8; w++) v += smv[w][e];
            if (v > bv) { bv = v; best = e; }
        }
        g_tile_id[t] = best;
#pragma unroll
        for (int e = 0; e < NTILES; e++) gate_out[(size_t)t * NTILES + e] = (e == best) ? 1.f : 0.f;
        atomicAdd(&g_cnt[best], 1);
    }
}

__global__ void scan_kernel() {
    if (threadIdx.x == 0) {
        int a = 0;
        for (int e = 0; e < NTILES; e++) { g_off[e] = a; a += g_cnt[e]; }
    }
}

__global__ void scatter_kernel() {
    int t = blockIdx.x * 256 + threadIdx.x;
    int e = g_tile_id[t];
    int p = atomicAdd(&g_fill[e], 1);
    g_perm[g_off[e] + p] = t;
}

// ---------------- launch --------------------------------------------------------
extern "C" void kernel_launch(void* const* d_in, const int* in_sizes, int n_in,
                              void* d_out, int out_size) {
    const float* x      = (const float*)d_in[0];
    const float* ln1_g  = (const float*)d_in[1];
    const float* ln1_b  = (const float*)d_in[2];
    const float* qkv_w  = (const float*)d_in[3];
    const float* qkv_b  = (const float*)d_in[4];
    const float* out_w  = (const float*)d_in[5];
    const float* out_b  = (const float*)d_in[6];
    const float* ln2_g  = (const float*)d_in[7];
    const float* ln2_b  = (const float*)d_in[8];
    const float* gate_w = (const float*)d_in[9];
    const float* gate_b = (const float*)d_in[10];
    const float* up_W   = (const float*)d_in[11];
    const float* up_b   = (const float*)d_in[12];
    const float* down_W = (const float*)d_in[13];
    const float* down_b = (const float*)d_in[14];

    float* outp = (float*)d_out;
    float* gate_out = outp + (size_t)NTOK * DMODEL;

    void* p;
    cudaGetSymbolAddress(&p, g_n1);   float* n1   = (float*)p;
    cudaGetSymbolAddress(&p, g_qkv);  float* qkv  = (float*)p;
    cudaGetSymbolAddress(&p, g_attn); float* attn = (float*)p;
    cudaGetSymbolAddress(&p, g_xres); float* xres = (float*)p;
    cudaGetSymbolAddress(&p, g_n2);   float* n2   = (float*)p;
    cudaGetSymbolAddress(&p, g_h_hi); __nv_bfloat16* hh = (__nv_bfloat16*)p;
    cudaGetSymbolAddress(&p, g_h_lo); __nv_bfloat16* hl = (__nv_bfloat16*)p;

    // 1) LN1
    ln_kernel<<<NTOK, 256>>>(x, ln1_g, ln1_b, n1);
    // 2) QKV projection (HMMA)
    mma_gemm_nt<false><<<dim3(D3 / 128, NTOK / 128), 256>>>(n1, qkv_w, qkv_b, nullptr, qkv,
                                                            D3, DMODEL);
    // 3) attention (fp32)
    const int smem_attn = (4096 + 4096 + 64 * 68 + 64 * 68) * 4;
    cudaFuncSetAttribute(attn_kernel, cudaFuncAttributeMaxDynamicSharedMemorySize, smem_attn);
    attn_kernel<<<dim3(SEQ / 64, NHEAD, NB), 256, smem_attn>>>(qkv, attn);
    // 4) out projection + residual (HMMA)
    mma_gemm_nt<true><<<dim3(DMODEL / 128, NTOK / 128), 256>>>(attn, out_w, out_b, x, xres,
                                                               DMODEL, DMODEL);
    // 5) LN2
    ln_kernel<<<NTOK, 256>>>(xres, ln2_g, ln2_b, n2);
    // 6) gate + bucketing
    zero_kernel<<<1, 32>>>();
    gate_kernel<<<NTOK, 256>>>(n2, gate_w, gate_b, gate_out);
    scan_kernel<<<1, 32>>>();
    scatter_kernel<<<NTOK / 256, 256>>>();
    // 7) FFN (HMMA)
    mma_ffn_up<<<dim3(DFF / 128, NTOK / 128, NTILES), 256>>>(n2, up_W, up_b, hh, hl);
    mma_ffn_down<<<dim3(DMODEL / 128, NTOK / 128, NTILES), 256>>>(hh, hl, down_W, down_b,
                                                                  xres, outp);
}

// round 3
// speedup vs baseline: 2.6172x; 1.4660x over previous
#include <cuda_runtime.h>
#include <cuda_bf16.h>
#include <math.h>
#include <stdint.h>

#define NTOK 4096
#define DMODEL 1024
#define D3 3072
#define NHEAD 16
#define HDIM 64
#define SEQ 1024
#define NB 4
#define NTILES 8
#define DFF 4096

// ---------------- scratch ----------------------------------------------------
__device__ float g_n1[NTOK * DMODEL];
__device__ float g_qkv[NTOK * D3];
__device__ float g_attn[NTOK * DMODEL];
__device__ float g_xres[NTOK * DMODEL];
__device__ float g_n2[NTOK * DMODEL];
__device__ __nv_bfloat16 g_h_hi[(size_t)NTOK * DFF];
__device__ __nv_bfloat16 g_h_lo[(size_t)NTOK * DFF];
__device__ int g_tile_id[NTOK];
__device__ int g_perm[NTOK];
__device__ int g_cnt[NTILES];
__device__ int g_off[NTILES];
__device__ int g_fill[NTILES];

// ---------------- mma helpers -------------------------------------------------
__device__ __forceinline__ uint32_t sptr(const void* p) {
    return (uint32_t)__cvta_generic_to_shared(p);
}
__device__ __forceinline__ void ldsm4(uint32_t* r, uint32_t a) {
    asm volatile("ldmatrix.sync.aligned.m8n8.x4.shared.b16 {%0,%1,%2,%3}, [%4];"
                 : "=r"(r[0]), "=r"(r[1]), "=r"(r[2]), "=r"(r[3]) : "r"(a));
}
__device__ __forceinline__ void ldsm4t(uint32_t* r, uint32_t a) {
    asm volatile("ldmatrix.sync.aligned.m8n8.x4.trans.shared.b16 {%0,%1,%2,%3}, [%4];"
                 : "=r"(r[0]), "=r"(r[1]), "=r"(r[2]), "=r"(r[3]) : "r"(a));
}
__device__ __forceinline__ void mma16816(float* c, const uint32_t* a, const uint32_t* b) {
    asm volatile(
        "mma.sync.aligned.m16n8k16.row.col.f32.bf16.bf16.f32 "
        "{%0,%1,%2,%3}, {%4,%5,%6,%7}, {%8,%9}, {%0,%1,%2,%3};"
        : "+f"(c[0]), "+f"(c[1]), "+f"(c[2]), "+f"(c[3])
        : "r"(a[0]), "r"(a[1]), "r"(a[2]), "r"(a[3]), "r"(b[0]), "r"(b[1]));
}
__device__ __forceinline__ uint32_t pack_bf2(__nv_bfloat16 a, __nv_bfloat16 b) {
    return (uint32_t)__bfloat16_as_ushort(a) | ((uint32_t)__bfloat16_as_ushort(b) << 16);
}
__device__ __forceinline__ void split4(float4 v, __nv_bfloat16* hi, __nv_bfloat16* lo) {
    float a[4] = {v.x, v.y, v.z, v.w};
    __nv_bfloat16 h[4], l[4];
#pragma unroll
    for (int i = 0; i < 4; i++) {
        h[i] = __float2bfloat16(a[i]);
        l[i] = __float2bfloat16(a[i] - __bfloat162float(h[i]));
    }
    *(uint32_t*)(hi)     = pack_bf2(h[0], h[1]);
    *(uint32_t*)(hi + 2) = pack_bf2(h[2], h[3]);
    *(uint32_t*)(lo)     = pack_bf2(l[0], l[1]);
    *(uint32_t*)(lo + 2) = pack_bf2(l[2], l[3]);
}
__device__ __forceinline__ void split2_store(__nv_bfloat16* hi, __nv_bfloat16* lo,
                                             float v0, float v1) {
    __nv_bfloat16 h0 = __float2bfloat16(v0), h1 = __float2bfloat16(v1);
    __nv_bfloat16 l0 = __float2bfloat16(v0 - __bfloat162float(h0));
    __nv_bfloat16 l1 = __float2bfloat16(v1 - __bfloat162float(h1));
    *(uint32_t*)hi = pack_bf2(h0, h1);
    *(uint32_t*)lo = pack_bf2(l0, l1);
}
__device__ __forceinline__ void split_pack(float x, float y, uint32_t& hi, uint32_t& lo) {
    __nv_bfloat16 hx = __float2bfloat16(x), hy = __float2bfloat16(y);
    __nv_bfloat16 lx = __float2bfloat16(x - __bfloat162float(hx));
    __nv_bfloat16 ly = __float2bfloat16(y - __bfloat162float(hy));
    hi = pack_bf2(hx, hy);
    lo = pack_bf2(lx, ly);
}

// one 32-wide K step: 2 x k16 substeps, hi/lo compensated (3 mma passes)
template <bool BT, int BSTR>
__device__ __forceinline__ void mma_compute(const __nv_bfloat16* As_hi, const __nv_bfloat16* As_lo,
                                            const __nv_bfloat16* Bs_hi, const __nv_bfloat16* Bs_lo,
                                            float (*acc)[4][4], int lane, int wm, int wn) {
#pragma unroll
    for (int s = 0; s < 2; s++) {
        const int ks = s * 16;
        uint32_t ah[4][4], al[4][4], bh[4][2], bl[4][2];
#pragma unroll
        for (int mi = 0; mi < 4; mi++) {
            int row = wm * 64 + mi * 16 + (lane & 15);
            int col = ks + ((lane >> 4) & 1) * 8;
            ldsm4(ah[mi], sptr(As_hi + row * 40 + col));
            ldsm4(al[mi], sptr(As_lo + row * 40 + col));
        }
#pragma unroll
        for (int p = 0; p < 2; p++) {
            uint32_t r[4];
            uint32_t adr_h, adr_l;
            if (!BT) {
                int n = wn * 32 + p * 16 + ((lane >> 4) & 1) * 8 + (lane & 7);
                int col = ks + ((lane >> 3) & 1) * 8;
                adr_h = sptr(Bs_hi + n * BSTR + col);
                adr_l = sptr(Bs_lo + n * BSTR + col);
                ldsm4(r, adr_h);
            } else {
                int k = ks + ((lane >> 3) & 1) * 8 + (lane & 7);
                int n = wn * 32 + p * 16 + ((lane >> 4) & 1) * 8;
                adr_h = sptr(Bs_hi + k * BSTR + n);
                adr_l = sptr(Bs_lo + k * BSTR + n);
                ldsm4t(r, adr_h);
            }
            bh[2 * p][0] = r[0]; bh[2 * p][1] = r[1];
            bh[2 * p + 1][0] = r[2]; bh[2 * p + 1][1] = r[3];
            if (!BT) ldsm4(r, adr_l); else ldsm4t(r, adr_l);
            bl[2 * p][0] = r[0]; bl[2 * p][1] = r[1];
            bl[2 * p + 1][0] = r[2]; bl[2 * p + 1][1] = r[3];
        }
#pragma unroll
        for (int mi = 0; mi < 4; mi++)
#pragma unroll
            for (int ni = 0; ni < 4; ni++) {
                mma16816(acc[mi][ni], ah[mi], bh[ni]);
                mma16816(acc[mi][ni], ah[mi], bl[ni]);
                mma16816(acc[mi][ni], al[mi], bh[ni]);
            }
    }
}

// ---------------- NT GEMM (A [M,K], W [N,K]), 2-stage double buffered ---------
template <bool RESID>
__global__ __launch_bounds__(256, 1) void mma_gemm_nt(const float* __restrict__ A,
                                                      const float* __restrict__ W,
                                                      const float* __restrict__ bias,
                                                      const float* __restrict__ resid,
                                                      float* __restrict__ C, int N, int K) {
    extern __shared__ __nv_bfloat16 dsm[];
    const int STG = 20480;  // elems per stage: 4 * 128*40
    const int tid = threadIdx.x, lane = tid & 31, w = tid >> 5;
    const int wm = w & 1, wn = w >> 1;
    const int bm = blockIdx.y * 128, bn = blockIdx.x * 128;
    float acc[4][4][4] = {};
    float4 pa[4], pb[4];

    auto load_regs = [&](int kt) {
#pragma unroll
        for (int i = 0; i < 4; i++) {
            int idx = tid + i * 256, row = idx >> 3, kc = idx & 7;
            pa[i] = *(const float4*)(A + (size_t)(bm + row) * K + kt + kc * 4);
            pb[i] = *(const float4*)(W + (size_t)(bn + row) * K + kt + kc * 4);
        }
    };
    auto store_stage = [&](int s) {
        __nv_bfloat16* b0 = dsm + s * STG;
#pragma unroll
        for (int i = 0; i < 4; i++) {
            int idx = tid + i * 256, row = idx >> 3, kc = idx & 7;
            split4(pa[i], b0 + row * 40 + kc * 4, b0 + 5120 + row * 40 + kc * 4);
            split4(pb[i], b0 + 10240 + row * 40 + kc * 4, b0 + 15360 + row * 40 + kc * 4);
        }
    };

    load_regs(0);
    store_stage(0);
    __syncthreads();
    const int NIT = K >> 5;
    for (int it = 0; it < NIT; it++) {
        int cur = it & 1;
        bool more = (it + 1 < NIT);
        if (more) load_regs((it + 1) * 32);
        __nv_bfloat16* b0 = dsm + cur * STG;
        mma_compute<false, 40>(b0, b0 + 5120, b0 + 10240, b0 + 15360, acc, lane, wm, wn);
        if (more) store_stage(cur ^ 1);
        __syncthreads();
    }
#pragma unroll
    for (int mi = 0; mi < 4; mi++) {
        int r0 = bm + wm * 64 + mi * 16 + (lane >> 2);
#pragma unroll
        for (int ni = 0; ni < 4; ni++) {
            int cn = bn + wn * 32 + ni * 8 + (lane & 3) * 2;
            float2 bs = *(const float2*)(bias + cn);
            float2 o0 = make_float2(acc[mi][ni][0] + bs.x, acc[mi][ni][1] + bs.y);
            float2 o1 = make_float2(acc[mi][ni][2] + bs.x, acc[mi][ni][3] + bs.y);
            if (RESID) {
                float2 ra = *(const float2*)(resid + (size_t)r0 * N + cn);
                float2 rb = *(const float2*)(resid + (size_t)(r0 + 8) * N + cn);
                o0.x += ra.x; o0.y += ra.y; o1.x += rb.x; o1.y += rb.y;
            }
            *(float2*)(C + (size_t)r0 * N + cn) = o0;
            *(float2*)(C + (size_t)(r0 + 8) * N + cn) = o1;
        }
    }
}

// ---------------- FFN up (B [K,N] trans), 2-stage double buffered -------------
__global__ __launch_bounds__(256, 1) void mma_ffn_up(const float* __restrict__ n2,
                                                     const float* __restrict__ upW,
                                                     const float* __restrict__ upb,
                                                     __nv_bfloat16* __restrict__ Hh,
                                                     __nv_bfloat16* __restrict__ Hl) {
    const int t = blockIdx.z;
    const int cnt = g_cnt[t];
    const int bm = blockIdx.y * 128;
    if (bm >= cnt) return;
    const int off = g_off[t];
    const int bn = blockIdx.x * 128;
    const float* B = upW + (size_t)t * DMODEL * DFF;
    extern __shared__ __nv_bfloat16 dsm[];
    const int STG = 18944;  // 2*5120 (A hi/lo) + 2*4352 (B hi/lo)
    const int tid = threadIdx.x, lane = tid & 31, w = tid >> 5;
    const int wm = w & 1, wn = w >> 1;
    float acc[4][4][4] = {};
    int tokA[4];
#pragma unroll
    for (int i = 0; i < 4; i++) {
        int idx = tid + i * 256, row = idx >> 3, gr = bm + row;
        tokA[i] = (gr < cnt) ? g_perm[off + gr] : -1;
    }
    float4 pa[4], pb[4];
    auto load_regs = [&](int kt) {
#pragma unroll
        for (int i = 0; i < 4; i++) {
            int idx = tid + i * 256, kc = idx & 7;
            pa[i] = (tokA[i] >= 0)
                        ? *(const float4*)(n2 + (size_t)tokA[i] * DMODEL + kt + kc * 4)
                        : make_float4(0.f, 0.f, 0.f, 0.f);
            int k = idx >> 5, nc = idx & 31;
            pb[i] = *(const float4*)(B + (size_t)(kt + k) * DFF + bn + nc * 4);
        }
    };
    auto store_stage = [&](int s) {
        __nv_bfloat16* b0 = dsm + s * STG;
#pragma unroll
        for (int i = 0; i < 4; i++) {
            int idx = tid + i * 256, row = idx >> 3, kc = idx & 7;
            split4(pa[i], b0 + row * 40 + kc * 4, b0 + 5120 + row * 40 + kc * 4);
            int k = idx >> 5, nc = idx & 31;
            split4(pb[i], b0 + 10240 + k * 136 + nc * 4, b0 + 14592 + k * 136 + nc * 4);
        }
    };
    load_regs(0);
    store_stage(0);
    __syncthreads();
    const int NIT = DMODEL >> 5;
    for (int it = 0; it < NIT; it++) {
        int cur = it & 1;
        bool more = (it + 1 < NIT);
        if (more) load_regs((it + 1) * 32);
        __nv_bfloat16* b0 = dsm + cur * STG;
        mma_compute<true, 136>(b0, b0 + 5120, b0 + 10240, b0 + 14592, acc, lane, wm, wn);
        if (more) store_stage(cur ^ 1);
        __syncthreads();
    }
#pragma unroll
    for (int mi = 0; mi < 4; mi++) {
        int r0 = bm + wm * 64 + mi * 16 + (lane >> 2);
#pragma unroll
        for (int ni = 0; ni < 4; ni++) {
            int cn = bn + wn * 32 + ni * 8 + (lane & 3) * 2;
            float2 bs = *(const float2*)(upb + (size_t)t * DFF + cn);
            if (r0 < cnt) {
                float v0 = fmaxf(acc[mi][ni][0] + bs.x, 0.f);
                float v1 = fmaxf(acc[mi][ni][1] + bs.y, 0.f);
                split2_store(Hh + (size_t)(off + r0) * DFF + cn,
                             Hl + (size_t)(off + r0) * DFF + cn, v0, v1);
            }
            if (r0 + 8 < cnt) {
                float v2 = fmaxf(acc[mi][ni][2] + bs.x, 0.f);
                float v3 = fmaxf(acc[mi][ni][3] + bs.y, 0.f);
                split2_store(Hh + (size_t)(off + r0 + 8) * DFF + cn,
                             Hl + (size_t)(off + r0 + 8) * DFF + cn, v2, v3);
            }
        }
    }
}

// ---------------- FFN down (A pre-split bf16), 2-stage double buffered --------
__global__ __launch_bounds__(256, 1) void mma_ffn_down(const __nv_bfloat16* __restrict__ Hh,
                                                       const __nv_bfloat16* __restrict__ Hl,
                                                       const float* __restrict__ dW,
                                                       const float* __restrict__ db,
                                                       const float* __restrict__ xres,
                                                       float* __restrict__ outp) {
    const int t = blockIdx.z;
    const int cnt = g_cnt[t];
    const int bm = blockIdx.y * 128;
    if (bm >= cnt) return;
    const int off = g_off[t];
    const int bn = blockIdx.x * 128;
    const float* B = dW + (size_t)t * DFF * DMODEL;
    extern __shared__ __nv_bfloat16 dsm[];
    const int STG = 18944;
    const int tid = threadIdx.x, lane = tid & 31, w = tid >> 5;
    const int wm = w & 1, wn = w >> 1;
    float acc[4][4][4] = {};
    uint4 pah[2], pal[2];
    float4 pb[4];
    const uint4 z4 = make_uint4(0, 0, 0, 0);
    auto load_regs = [&](int kt) {
#pragma unroll
        for (int i = 0; i < 2; i++) {
            int idx = tid + i * 256, row = idx >> 2, kc = idx & 3, gr = bm + row;
            if (gr < cnt) {
                pah[i] = *(const uint4*)(Hh + (size_t)(off + gr) * DFF + kt + kc * 8);
                pal[i] = *(const uint4*)(Hl + (size_t)(off + gr) * DFF + kt + kc * 8);
            } else { pah[i] = z4; pal[i] = z4; }
        }
#pragma unroll
        for (int i = 0; i < 4; i++) {
            int idx = tid + i * 256, k = idx >> 5, nc = idx & 31;
            pb[i] = *(const float4*)(B + (size_t)(kt + k) * DMODEL + bn + nc * 4);
        }
    };
    auto store_stage = [&](int s) {
        __nv_bfloat16* b0 = dsm + s * STG;
#pragma unroll
        for (int i = 0; i < 2; i++) {
            int idx = tid + i * 256, row = idx >> 2, kc = idx & 3;
            *(uint4*)(b0 + row * 40 + kc * 8) = pah[i];
            *(uint4*)(b0 + 5120 + row * 40 + kc * 8) = pal[i];
        }
#pragma unroll
        for (int i = 0; i < 4; i++) {
            int idx = tid + i * 256, k = idx >> 5, nc = idx & 31;
            split4(pb[i], b0 + 10240 + k * 136 + nc * 4, b0 + 14592 + k * 136 + nc * 4);
        }
    };
    load_regs(0);
    store_stage(0);
    __syncthreads();
    const int NIT = DFF >> 5;
    for (int it = 0; it < NIT; it++) {
        int cur = it & 1;
        bool more = (it + 1 < NIT);
        if (more) load_regs((it + 1) * 32);
        __nv_bfloat16* b0 = dsm + cur * STG;
        mma_compute<true, 136>(b0, b0 + 5120, b0 + 10240, b0 + 14592, acc, lane, wm, wn);
        if (more) store_stage(cur ^ 1);
        __syncthreads();
    }
#pragma unroll
    for (int mi = 0; mi < 4; mi++) {
        int r0 = bm + wm * 64 + mi * 16 + (lane >> 2);
#pragma unroll
        for (int ni = 0; ni < 4; ni++) {
            int cn = bn + wn * 32 + ni * 8 + (lane & 3) * 2;
            float2 db2 = *(const float2*)(db + (size_t)t * DMODEL + cn);
            if (r0 < cnt) {
                int tok = g_perm[off + r0];
                float2 xr = *(const float2*)(xres + (size_t)tok * DMODEL + cn);
                *(float2*)(outp + (size_t)tok * DMODEL + cn) =
                    make_float2(acc[mi][ni][0] + db2.x + xr.x, acc[mi][ni][1] + db2.y + xr.y);
            }
            if (r0 + 8 < cnt) {
                int tok = g_perm[off + r0 + 8];
                float2 xr = *(const float2*)(xres + (size_t)tok * DMODEL + cn);
                *(float2*)(outp + (size_t)tok * DMODEL + cn) =
                    make_float2(acc[mi][ni][2] + db2.x + xr.x, acc[mi][ni][3] + db2.y + xr.y);
            }
        }
    }
}

// ---------------- MMA flash attention (compensated bf16) ----------------------
// block: (qt, h, b), 128 threads (4 warps), each warp 16 q rows.
// smem: Qh,Ql,Kh,Kl,Vh,Vl each [64][72] bf16 (stride 72 = 9x16B, odd -> no conflicts)
__global__ __launch_bounds__(128) void attn_mma(const float* __restrict__ qkv,
                                                float* __restrict__ outp) {
    extern __shared__ __nv_bfloat16 asm_[];
    __nv_bfloat16* Qh = asm_;
    __nv_bfloat16* Ql = asm_ + 4608;
    __nv_bfloat16* Kh = asm_ + 9216;
    __nv_bfloat16* Kl = asm_ + 13824;
    __nv_bfloat16* Vh = asm_ + 18432;
    __nv_bfloat16* Vl = asm_ + 23040;

    const int qt = blockIdx.x, h = blockIdx.y, b = blockIdx.z;
    const int tid = threadIdx.x, lane = tid & 31, wid = tid >> 5;
    const int tok0 = b * SEQ + qt * 64;
    const int wq = wid * 16;

    // load Q (scaled by 1/sqrt(hd)=0.125), split hi/lo
#pragma unroll
    for (int i = 0; i < 8; i++) {
        int idx = i * 128 + tid;
        int row = idx >> 4, col = (idx & 15) * 4;
        float4 v = *(const float4*)(qkv + (size_t)(tok0 + row) * D3 + h * HDIM + col);
        v.x *= 0.125f; v.y *= 0.125f; v.z *= 0.125f; v.w *= 0.125f;
        split4(v, Qh + row * 72 + col, Ql + row * 72 + col);
    }

    float m_[2] = {-1e30f, -1e30f}, l_[2] = {0.f, 0.f};
    float O[8][4] = {};

    for (int kt = 0; kt < 16; kt++) {
        int kb = b * SEQ + kt * 64;
        __syncthreads();  // previous iteration's reads of K/V done
#pragma unroll
        for (int i = 0; i < 8; i++) {
            int idx = i * 128 + tid;
            int row = idx >> 4, col = (idx & 15) * 4;
            const float* base = qkv + (size_t)(kb + row) * D3 + h * HDIM + col;
            float4 kv = *(const float4*)(base + DMODEL);
            split4(kv, Kh + row * 72 + col, Kl + row * 72 + col);
            float4 vv = *(const float4*)(base + 2 * DMODEL);
            split4(vv, Vh + row * 72 + col, Vl + row * 72 + col);
        }
        __syncthreads();

        // S = Q K^T (16 x 64 per warp), compensated
        float S[8][4] = {};
#pragma unroll
        for (int ks = 0; ks < 4; ks++) {
            uint32_t qh[4], ql[4], kh[8][2], kl[8][2];
            {
                int row = wq + (lane & 15);
                int col = ks * 16 + ((lane >> 4) & 1) * 8;
                ldsm4(qh, sptr(Qh + row * 72 + col));
                ldsm4(ql, sptr(Ql + row * 72 + col));
            }
#pragma unroll
            for (int p = 0; p < 4; p++) {
                uint32_t r[4];
                int n = p * 16 + ((lane >> 4) & 1) * 8 + (lane & 7);
                int col = ks * 16 + ((lane >> 3) & 1) * 8;
                ldsm4(r, sptr(Kh + n * 72 + col));
                kh[2 * p][0] = r[0]; kh[2 * p][1] = r[1];
                kh[2 * p + 1][0] = r[2]; kh[2 * p + 1][1] = r[3];
                ldsm4(r, sptr(Kl + n * 72 + col));
                kl[2 * p][0] = r[0]; kl[2 * p][1] = r[1];
                kl[2 * p + 1][0] = r[2]; kl[2 * p + 1][1] = r[3];
            }
#pragma unroll
            for (int j = 0; j < 8; j++) {
                mma16816(S[j], qh, kh[j]);
                mma16816(S[j], qh, kl[j]);
                mma16816(S[j], ql, kh[j]);
            }
        }

        // online softmax (rows: lane>>2 and +8)
        float fac[2];
#pragma unroll
        for (int h2 = 0; h2 < 2; h2++) {
            float rm = -1e30f;
#pragma unroll
            for (int j = 0; j < 8; j++)
                rm = fmaxf(rm, fmaxf(S[j][2 * h2], S[j][2 * h2 + 1]));
            rm = fmaxf(rm, __shfl_xor_sync(0xffffffffu, rm, 1));
            rm = fmaxf(rm, __shfl_xor_sync(0xffffffffu, rm, 2));
            float mn = fmaxf(m_[h2], rm);
            fac[h2] = __expf(m_[h2] - mn);
            float rsum = 0.f;
#pragma unroll
            for (int j = 0; j < 8; j++) {
                float p0 = __expf(S[j][2 * h2] - mn);
                float p1 = __expf(S[j][2 * h2 + 1] - mn);
                S[j][2 * h2] = p0; S[j][2 * h2 + 1] = p1;
                rsum += p0 + p1;
            }
            rsum += __shfl_xor_sync(0xffffffffu, rsum, 1);
            rsum += __shfl_xor_sync(0xffffffffu, rsum, 2);
            l_[h2] = l_[h2] * fac[h2] + rsum;
            m_[h2] = mn;
        }
#pragma unroll
        for (int j = 0; j < 8; j++) {
            O[j][0] *= fac[0]; O[j][1] *= fac[0];
            O[j][2] *= fac[1]; O[j][3] *= fac[1];
        }

        // O += P V, compensated; P a-frags built from S register layout
#pragma unroll
        for (int ks = 0; ks < 4; ks++) {
            uint32_t ph[4], pl[4];
            split_pack(S[2 * ks][0], S[2 * ks][1], ph[0], pl[0]);
            split_pack(S[2 * ks][2], S[2 * ks][3], ph[1], pl[1]);
            split_pack(S[2 * ks + 1][0], S[2 * ks + 1][1], ph[2], pl[2]);
            split_pack(S[2 * ks + 1][2], S[2 * ks + 1][3], ph[3], pl[3]);
            uint32_t vh[8][2], vl[8][2];
#pragma unroll
            for (int p = 0; p < 4; p++) {
                uint32_t r[4];
                int k = ks * 16 + ((lane >> 3) & 1) * 8 + (lane & 7);
                int n = p * 16 + ((lane >> 4) & 1) * 8;
                ldsm4t(r, sptr(Vh + k * 72 + n));
                vh[2 * p][0] = r[0]; vh[2 * p][1] = r[1];
                vh[2 * p + 1][0] = r[2]; vh[2 * p + 1][1] = r[3];
                ldsm4t(r, sptr(Vl + k * 72 + n));
                vl[2 * p][0] = r[0]; vl[2 * p][1] = r[1];
                vl[2 * p + 1][0] = r[2]; vl[2 * p + 1][1] = r[3];
            }
#pragma unroll
            for (int j = 0; j < 8; j++) {
                mma16816(O[j], ph, vh[j]);
                mma16816(O[j], ph, vl[j]);
                mma16816(O[j], pl, vh[j]);
            }
        }
    }

    float inv0 = 1.f / l_[0], inv1 = 1.f / l_[1];
    int r0 = tok0 + wq + (lane >> 2);
#pragma unroll
    for (int j = 0; j < 8; j++) {
        int col = h * HDIM + j * 8 + (lane & 3) * 2;
        *(float2*)(outp + (size_t)r0 * DMODEL + col) =
            make_float2(O[j][0] * inv0, O[j][1] * inv0);
        *(float2*)(outp + (size_t)(r0 + 8) * DMODEL + col) =
            make_float2(O[j][2] * inv1, O[j][3] * inv1);
    }
}

// ---------------- layernorm ---------------------------------------------------
__global__ void ln_kernel(const float* __restrict__ x, const float* __restrict__ g,
                          const float* __restrict__ bb, float* __restrict__ y) {
    int t = blockIdx.x;
    const float* xr = x + (size_t)t * DMODEL;
    float s = 0.f, s2 = 0.f;
#pragma unroll
    for (int i = 0; i < 4; i++) {
        float v = xr[threadIdx.x + i * 256];
        s += v; s2 += v * v;
    }
#pragma unroll
    for (int o = 16; o; o >>= 1) {
        s += __shfl_xor_sync(0xffffffffu, s, o);
        s2 += __shfl_xor_sync(0xffffffffu, s2, o);
    }
    __shared__ float rs[8], rq[8];
    if ((threadIdx.x & 31) == 0) { rs[threadIdx.x >> 5] = s; rq[threadIdx.x >> 5] = s2; }
    __syncthreads();
    __shared__ float smean, srstd;
    if (threadIdx.x == 0) {
        float a = 0.f, b2 = 0.f;
#pragma unroll
        for (int i = 0; i < 8; i++) { a += rs[i]; b2 += rq[i]; }
        float mean = a * (1.f / DMODEL);
        float var = b2 * (1.f / DMODEL) - mean * mean;
        smean = mean; srstd = rsqrtf(var + 1e-5f);
    }
    __syncthreads();
    float mean = smean, rstd = srstd;
    float* yr = y + (size_t)t * DMODEL;
#pragma unroll
    for (int i = 0; i < 4; i++) {
        int d = threadIdx.x + i * 256;
        yr[d] = (xr[d] - mean) * rstd * g[d] + bb[d];
    }
}

// ---------------- gate / bucketing --------------------------------------------
__global__ void zero_kernel() {
    if (threadIdx.x < NTILES) { g_cnt[threadIdx.x] = 0; g_fill[threadIdx.x] = 0; }
}

__global__ void gate_kernel(const float* __restrict__ n2, const float* __restrict__ gw,
                            const float* __restrict__ gb, float* __restrict__ gate_out) {
    int t = blockIdx.x;
    const float* xr = n2 + (size_t)t * DMODEL;
    float lg[NTILES] = {};
    for (int d = threadIdx.x; d < DMODEL; d += 256) {
        float v = xr[d];
#pragma unroll
        for (int e = 0; e < NTILES; e++) lg[e] += v * gw[e * DMODEL + d];
    }
#pragma unroll
    for (int o = 16; o; o >>= 1)
#pragma unroll
        for (int e = 0; e < NTILES; e++) lg[e] += __shfl_xor_sync(0xffffffffu, lg[e], o);
    __shared__ float smv[8][NTILES];
    if ((threadIdx.x & 31) == 0)
#pragma unroll
        for (int e = 0; e < NTILES; e++) smv[threadIdx.x >> 5][e] = lg[e];
    __syncthreads();
    if (threadIdx.x == 0) {
        int best = 0; float bv = -1e30f;
#pragma unroll
        for (int e = 0; e < NTILES; e++) {
            float v = gb[e];
#pragma unroll
            for (int w = 0; w < 8; w++) v += smv[w][e];
            if (v > bv) { bv = v; best = e; }
        }
        g_tile_id[t] = best;
#pragma unroll
        for (int e = 0; e < NTILES; e++) gate_out[(size_t)t * NTILES + e] = (e == best) ? 1.f : 0.f;
        atomicAdd(&g_cnt[best], 1);
    }
}

__global__ void scan_kernel() {
    if (threadIdx.x == 0) {
        int a = 0;
        for (int e = 0; e < NTILES; e++) { g_off[e] = a; a += g_cnt[e]; }
    }
}

__global__ void scatter_kernel() {
    int t = blockIdx.x * 256 + threadIdx.x;
    int e = g_tile_id[t];
    int p = atomicAdd(&g_fill[e], 1);
    g_perm[g_off[e] + p] = t;
}

// ---------------- launch --------------------------------------------------------
extern "C" void kernel_launch(void* const* d_in, const int* in_sizes, int n_in,
                              void* d_out, int out_size) {
    const float* x      = (const float*)d_in[0];
    const float* ln1_g  = (const float*)d_in[1];
    const float* ln1_b  = (const float*)d_in[2];
    const float* qkv_w  = (const float*)d_in[3];
    const float* qkv_b  = (const float*)d_in[4];
    const float* out_w  = (const float*)d_in[5];
    const float* out_b  = (const float*)d_in[6];
    const float* ln2_g  = (const float*)d_in[7];
    const float* ln2_b  = (const float*)d_in[8];
    const float* gate_w = (const float*)d_in[9];
    const float* gate_b = (const float*)d_in[10];
    const float* up_W   = (const float*)d_in[11];
    const float* up_b   = (const float*)d_in[12];
    const float* down_W = (const float*)d_in[13];
    const float* down_b = (const float*)d_in[14];

    float* outp = (float*)d_out;
    float* gate_out = outp + (size_t)NTOK * DMODEL;

    void* p;
    cudaGetSymbolAddress(&p, g_n1);   float* n1   = (float*)p;
    cudaGetSymbolAddress(&p, g_qkv);  float* qkv  = (float*)p;
    cudaGetSymbolAddress(&p, g_attn); float* attn = (float*)p;
    cudaGetSymbolAddress(&p, g_xres); float* xres = (float*)p;
    cudaGetSymbolAddress(&p, g_n2);   float* n2   = (float*)p;
    cudaGetSymbolAddress(&p, g_h_hi); __nv_bfloat16* hh = (__nv_bfloat16*)p;
    cudaGetSymbolAddress(&p, g_h_lo); __nv_bfloat16* hl = (__nv_bfloat16*)p;

    const int smem_gemm = 2 * 20480 * 2;   // 81920 B
    const int smem_ffn  = 2 * 18944 * 2;   // 75776 B
    const int smem_attn = 27648 * 2;       // 55296 B
    cudaFuncSetAttribute(mma_gemm_nt<false>, cudaFuncAttributeMaxDynamicSharedMemorySize, smem_gemm);
    cudaFuncSetAttribute(mma_gemm_nt<true>, cudaFuncAttributeMaxDynamicSharedMemorySize, smem_gemm);
    cudaFuncSetAttribute(mma_ffn_up, cudaFuncAttributeMaxDynamicSharedMemorySize, smem_ffn);
    cudaFuncSetAttribute(mma_ffn_down, cudaFuncAttributeMaxDynamicSharedMemorySize, smem_ffn);
    cudaFuncSetAttribute(attn_mma, cudaFuncAttributeMaxDynamicSharedMemorySize, smem_attn);

    // 1) LN1
    ln_kernel<<<NTOK, 256>>>(x, ln1_g, ln1_b, n1);
    // 2) QKV projection
    mma_gemm_nt<false><<<dim3(D3 / 128, NTOK / 128), 256, smem_gemm>>>(n1, qkv_w, qkv_b,
                                                                       nullptr, qkv, D3, DMODEL);
    // 3) attention (compensated bf16 MMA)
    attn_mma<<<dim3(SEQ / 64, NHEAD, NB), 128, smem_attn>>>(qkv, attn);
    // 4) out projection + residual
    mma_gemm_nt<true><<<dim3(DMODEL / 128, NTOK / 128), 256, smem_gemm>>>(attn, out_w, out_b,
                                                                          x, xres, DMODEL, DMODEL);
    // 5) LN2
    ln_kernel<<<NTOK, 256>>>(xres, ln2_g, ln2_b, n2);
    // 6) gate + bucketing
    zero_kernel<<<1, 32>>>();
    gate_kernel<<<NTOK, 256>>>(n2, gate_w, gate_b, gate_out);
    scan_kernel<<<1, 32>>>();
    scatter_kernel<<<NTOK / 256, 256>>>();
    // 7) FFN
    mma_ffn_up<<<dim3(DFF / 128, NTOK / 128, NTILES), 256, smem_ffn>>>(n2, up_W, up_b, hh, hl);
    mma_ffn_down<<<dim3(DMODEL / 128, NTOK / 128, NTILES), 256, smem_ffn>>>(hh, hl, down_W,
                                                                            down_b, xres, outp);
}